// round 10
// baseline (speedup 1.0000x reference)
#include <cuda_runtime.h>
#include <cstdint>

#define N_ANCH 25200
#define NBATCH 16
#define NCLS 80

// -------- device scratch (no allocation allowed) --------
__device__ float g_scores[(size_t)NBATCH * NCLS * N_ANCH];   // class-major scores
__device__ float g_boxes[(size_t)NBATCH * N_ANCH * 4];       // decoded boxes
__device__ float g_cls_s[(size_t)NBATCH * NCLS * 100];       // per-class NMS survivors: scores
__device__ float g_cls_b[(size_t)NBATCH * NCLS * 100 * 4];   // per-class NMS survivors: boxes

__constant__ float c_anch[18] = {10,13, 16,30, 33,23, 30,61, 62,45, 59,119, 116,90, 156,198, 373,326};

__device__ __forceinline__ float sigmoidf(float x) { return 1.0f / (1.0f + expf(-x)); }

// ======================= Kernel 1: decode + transpose =======================
// Tile = 120 consecutive anchors within one level (level sizes 19200/4800/1200
// are all divisible by 120, and anchor-major order is byte-contiguous in the
// input: element = base + m*85 + ch).
__global__ void __launch_bounds__(256) k_decode(const float* __restrict__ p3,
                                                const float* __restrict__ p4,
                                                const float* __restrict__ p5) {
    __shared__ float s_sc[NCLS * 121];   // [class][anchor], pad 121 -> conflict-free
    __shared__ float s_obj[120];

    int tile = blockIdx.x % 210;
    int b    = blockIdx.x / 210;

    const float* base;
    int W, m0, n0, abase;
    float stride;
    if (tile < 160)      { base = p3 + (size_t)b * 1632000; W = 80; m0 = tile * 120;        n0 = m0;         abase = 0; stride = 8.0f;  }
    else if (tile < 200) { base = p4 + (size_t)b * 408000;  W = 40; m0 = (tile - 160) * 120; n0 = 19200 + m0; abase = 3; stride = 16.0f; }
    else                 { base = p5 + (size_t)b * 102000;  W = 20; m0 = (tile - 200) * 120; n0 = 24000 + m0; abase = 6; stride = 32.0f; }

    const float* src = base + (size_t)m0 * 85;
    int t = threadIdx.x;

    if (t < 120) {
        int m = m0 + t;
        int a = m % 3;
        int cell = m / 3;
        int w = cell % W;
        int h = cell / W;
        const float* e = src + t * 85;
        float sx = sigmoidf(e[0]);
        float sy = sigmoidf(e[1]);
        float bw = expf(e[2]) * c_anch[(abase + a) * 2 + 0];
        float bh = expf(e[3]) * c_anch[(abase + a) * 2 + 1];
        float cx = (sx + (float)w) * stride;
        float cy = (sy + (float)h) * stride;
        float4 box = make_float4(cx - bw * 0.5f, cy - bh * 0.5f, cx + bw * 0.5f, cy + bh * 0.5f);
        ((float4*)g_boxes)[(size_t)b * N_ANCH + n0 + t] = box;
        s_obj[t] = sigmoidf(e[4]);
    }
    __syncthreads();

    // scores: coalesced global reads (runs of 80), conflict-free smem writes
    for (int i = t; i < 120 * NCLS; i += 256) {
        int anc = i / NCLS;
        int c   = i % NCLS;
        float v = src[anc * 85 + 5 + c];
        s_sc[c * 121 + anc] = s_obj[anc] * sigmoidf(v);
    }
    __syncthreads();

    // coalesced transposed write: per class, 120 contiguous floats
    float* dst = g_scores + (size_t)b * NCLS * N_ANCH + n0;
    for (int i = t; i < 120 * NCLS; i += 256) {
        int c = i / 120;
        int k = i % 120;
        dst[(size_t)c * N_ANCH + k] = s_sc[c * 121 + k];
    }
}

// ======================= Kernel 2: top-128 + NMS per (image,class) =======================
#define BS2 512
#define LISTCAP 1024
#define SC_FLOATS 25216
#define OFF_LIST (SC_FLOATS * 4)          // 100864
#define OFF_HIST (OFF_LIST + LISTCAP * 8) // 109056
#define OFF_BX   (OFF_HIST + 512 * 4)     // 111104 (16B aligned)
#define OFF_AREA (OFF_BX + 128 * 16)      // 113152
#define OFF_CS   (OFF_AREA + 128 * 4)     // 113664
#define SMEM2    (OFF_CS + 128 * 4)       // 114176 -> 2 blocks/SM

__global__ void __launch_bounds__(BS2) k_nms() {
    extern __shared__ unsigned char smem[];
    float* sc   = (float*)smem;
    unsigned long long* list = (unsigned long long*)(smem + OFF_LIST);
    int*    hist = (int*)(smem + OFF_HIST);
    float4* s_bx = (float4*)(smem + OFF_BX);
    float*  s_area = (float*)(smem + OFF_AREA);
    float*  s_cs = (float*)(smem + OFF_CS);
    float*  iou  = (float*)smem;   // alias of sc, used after selection (64KB < 100KB)
    __shared__ int sh_T, sh_nlist;

    int tid = threadIdx.x;
    int b = blockIdx.x / NCLS;
    int c = blockIdx.x % NCLS;
    const float* col = g_scores + (size_t)(b * NCLS + c) * N_ANCH;

    for (int i = tid; i < 512; i += BS2) hist[i] = 0;
    if (tid == 0) sh_nlist = 0;
    __syncthreads();

    // pass 1: load column + histogram of float-bit bins over (0.25, 1.0)
    const float4* col4 = (const float4*)col;
    for (int i = tid; i < N_ANCH / 4; i += BS2) {
        float4 v = col4[i];
        ((float4*)sc)[i] = v;
        float vv[4] = {v.x, v.y, v.z, v.w};
        #pragma unroll
        for (int k = 0; k < 4; k++) {
            if (vv[k] > 0.25f) {
                unsigned bin = (__float_as_uint(vv[k]) - 0x3E800000u) >> 15;
                atomicAdd(&hist[min(bin, 511u)], 1);
            }
        }
    }
    __syncthreads();

    if (tid == 0) {
        int cum = 0, tt = 511;
        for (; tt >= 0; --tt) {
            int h = hist[tt];
            if (cum + h >= 128) break;
            cum += h;
        }
        sh_T = tt;  // -1 means: take all candidates
    }
    __syncthreads();
    int T = sh_T;

    // pass 2: collect all candidates in bins >= T
    for (int i = tid; i < N_ANCH; i += BS2) {
        float v = sc[i];
        if (v > 0.25f) {
            int bin = (int)min((__float_as_uint(v) - 0x3E800000u) >> 15, 511u);
            if (bin >= T) {
                int p = atomicAdd(&sh_nlist, 1);
                if (p < LISTCAP)
                    list[p] = ((unsigned long long)__float_as_uint(v) << 32)
                            | (unsigned long long)(0xFFFFFFFFu - (unsigned)i);
            }
        }
    }
    __syncthreads();
    int L = min(sh_nlist, LISTCAP);

    // dynamic sort width: smallest pow2 >= max(128, L).  All nonzero keys live
    // in list[0..L); [L..P) is zeroed; [P..1024) never read afterward.
    int P = 128;
    while (P < L) P <<= 1;

    for (int i = L + tid; i < P; i += BS2) list[i] = 0ull;
    __syncthreads();

    // bitonic sort (width P) descending by (score_bits, ~index) -> exact jax top_k order
    for (int k = 2; k <= P; k <<= 1) {
        for (int j = k >> 1; j > 0; j >>= 1) {
            for (int i = tid; i < P; i += BS2) {
                int ixj = i ^ j;
                if (ixj > i) {
                    unsigned long long a = list[i], bb = list[ixj];
                    bool dsc = ((i & k) == 0);
                    if ((a < bb) == dsc) { list[i] = bb; list[ixj] = a; }
                }
            }
            __syncthreads();
        }
    }

    // top 128 -> scores, boxes, areas
    if (tid < 128) {
        unsigned long long key = list[tid];
        float s;
        unsigned idx;
        if (key == 0ull) { s = -1.0f; idx = 0; }
        else {
            s = __uint_as_float((unsigned)(key >> 32));
            idx = 0xFFFFFFFFu - (unsigned)(key & 0xFFFFFFFFull);
        }
        s_cs[tid] = s;
        float4 bb = ((const float4*)g_boxes)[(size_t)b * N_ANCH + idx];
        s_bx[tid] = bb;
        s_area[tid] = (bb.z - bb.x) * (bb.w - bb.y);
    }
    __syncthreads();

    // full 128x128 IoU matrix (reuses score smem)
    for (int p = tid; p < 128 * 128; p += BS2) {
        int i = p >> 7, j = p & 127;
        float4 bi = s_bx[i], bj = s_bx[j];
        float lx = fmaxf(bi.x, bj.x), ly = fmaxf(bi.y, bj.y);
        float rx = fminf(bi.z, bj.z), ry = fminf(bi.w, bj.w);
        float w = fmaxf(rx - lx, 0.0f), h = fmaxf(ry - ly, 0.0f);
        float inter = w * h;
        iou[p] = inter / (s_area[i] + s_area[j] - inter + 1e-9f);
    }
    __syncthreads();

    // serial NMS in warp 0: lane owns j, j+32, j+64, j+96
    if (tid < 32) {
        int lane = tid;
        float sc0 = s_cs[lane], sc1 = s_cs[lane + 32], sc2 = s_cs[lane + 64], sc3 = s_cs[lane + 96];
        int k0 = 1, k1 = 1, k2 = 1, k3 = 1;
        for (int i = 0; i < 128; ++i) {
            int q = i >> 5, srcl = i & 31;
            int kvq = (q == 0) ? k0 : ((q == 1) ? k1 : ((q == 2) ? k2 : k3));
            int kv = __shfl_sync(0xffffffffu, kvq, srcl);
            if (kv && s_cs[i] > 0.0f) {
                const float* row = iou + i * 128;
                if (lane      > i) k0 &= !(row[lane]      > 0.45f);
                if (lane + 32 > i) k1 &= !(row[lane + 32] > 0.45f);
                if (lane + 64 > i) k2 &= !(row[lane + 64] > 0.45f);
                if (lane + 96 > i) k3 &= !(row[lane + 96] > 0.45f);
            }
        }
        // compact survivors (already descending) into first 100 slots
        float* outS = g_cls_s + (size_t)(b * NCLS + c) * 100;
        float4* outB = ((float4*)g_cls_b) + (size_t)(b * NCLS + c) * 100;
        int base = 0;
        float scs[4] = {sc0, sc1, sc2, sc3};
        int ks[4] = {k0, k1, k2, k3};
        #pragma unroll
        for (int q = 0; q < 4; ++q) {
            int j = lane + q * 32;
            int v = ks[q] && (scs[q] > 0.0f);
            unsigned m = __ballot_sync(0xffffffffu, v);
            if (v) {
                int pos = base + __popc(m & ((1u << lane) - 1u));
                if (pos < 100) { outS[pos] = scs[q]; outB[pos] = s_bx[j]; }
            }
            base += __popc(m);
        }
        int ns = min(base, 100);
        for (int p = ns + lane; p < 100; p += 32) {
            outS[p] = -1.0f;
            outB[p] = make_float4(0, 0, 0, 0);
        }
    }
}

// ======================= Kernel 3: per-image final top-100 =======================
#define BS3 1024
__global__ void __launch_bounds__(BS3) k_final(float* __restrict__ out) {
    extern __shared__ unsigned long long keys[];
    int tid = threadIdx.x;
    int b = blockIdx.x;
    const float* cs = g_cls_s + (size_t)b * 8000;

    for (int i = tid; i < 8192; i += BS3) {
        unsigned long long key = 0ull;
        if (i < 8000) {
            unsigned fb = __float_as_uint(cs[i]);
            unsigned m = (fb & 0x80000000u) ? ~fb : (fb | 0x80000000u);  // order-preserving map
            key = ((unsigned long long)m << 32) | (unsigned long long)(0xFFFFFFFFu - (unsigned)i);
        }
        keys[i] = key;
    }
    __syncthreads();

    for (int k = 2; k <= 8192; k <<= 1) {
        for (int j = k >> 1; j > 0; j >>= 1) {
            for (int i = tid; i < 8192; i += BS3) {
                int ixj = i ^ j;
                if (ixj > i) {
                    unsigned long long a = keys[i], bb = keys[ixj];
                    bool dsc = ((i & k) == 0);
                    if ((a < bb) == dsc) { keys[i] = bb; keys[ixj] = a; }
                }
            }
            __syncthreads();
        }
    }

    __shared__ int s_cnt;
    if (tid == 0) s_cnt = 0;
    __syncthreads();

    if (tid < 100) {
        unsigned long long key = keys[tid];
        unsigned m = (unsigned)(key >> 32);
        unsigned fb = (m & 0x80000000u) ? (m ^ 0x80000000u) : ~m;
        float v = __uint_as_float(fb);
        unsigned flat = 0xFFFFFFFFu - (unsigned)(key & 0xFFFFFFFFull);
        bool valid = (v > 0.0f) && (flat < 8000u);
        float4 box = make_float4(0, 0, 0, 0);
        float score = 0.0f, clsf = 0.0f;
        if (valid) {
            box = ((const float4*)g_cls_b)[(size_t)b * 8000 + flat];
            score = v;
            clsf = (float)(flat / 100u);
            atomicAdd(&s_cnt, 1);
        }
        ((float4*)out)[b * 100 + tid] = box;                 // boxes  [0, 6400)
        out[6400 + b * 100 + tid] = score;                   // scores [6400, 8000)
        out[8000 + b * 100 + tid] = clsf;                    // cls    [8000, 9600)
    }
    __syncthreads();
    if (tid == 0) out[9600 + b] = (float)s_cnt;              // n_valid [9600, 9616)
}

// ======================= launch =======================
extern "C" void kernel_launch(void* const* d_in, const int* in_sizes, int n_in,
                              void* d_out, int out_size) {
    const float* p3 = (const float*)d_in[0];
    const float* p4 = (const float*)d_in[1];
    const float* p5 = (const float*)d_in[2];
    float* out = (float*)d_out;

    cudaFuncSetAttribute(k_nms,   cudaFuncAttributeMaxDynamicSharedMemorySize, SMEM2);
    cudaFuncSetAttribute(k_final, cudaFuncAttributeMaxDynamicSharedMemorySize, 8192 * 8);

    k_decode<<<NBATCH * 210, 256>>>(p3, p4, p5);
    k_nms<<<NBATCH * NCLS, BS2, SMEM2>>>();
    k_final<<<NBATCH, BS3, 8192 * 8>>>(out);
}

// round 17
// speedup vs baseline: 1.9894x; 1.9894x over previous
#include <cuda_runtime.h>
#include <cstdint>

#define N_ANCH 25200
#define NBATCH 16
#define NCLS 80

// -------- device scratch (no allocation allowed) --------
__device__ float g_scores[(size_t)NBATCH * NCLS * N_ANCH];   // class-major scores
__device__ float g_boxes[(size_t)NBATCH * N_ANCH * 4];       // decoded boxes
__device__ float g_cls_s[(size_t)NBATCH * NCLS * 100];       // per-class NMS survivors: scores
__device__ float g_cls_b[(size_t)NBATCH * NCLS * 100 * 4];   // per-class NMS survivors: boxes

__constant__ float c_anch[18] = {10,13, 16,30, 33,23, 30,61, 62,45, 59,119, 116,90, 156,198, 373,326};

// EXACT numerics of the passing run (rel_err 1.6e-8) — do not change.
__device__ __forceinline__ float sigmoidf(float x) { return 1.0f / (1.0f + expf(-x)); }

__device__ __forceinline__ int binof(float v) {
    return (int)min((__float_as_uint(v) - 0x3E800000u) >> 15, 511u);
}

// ======================= Kernel 1: decode + transpose =======================
// 120-anchor tile. One cooperative float4 sweep reads all 120*85 channels
// coalesced; ch0-3 staged raw, ch4 -> sigmoid obj, ch5.. -> sigmoid cls.
// obj multiply deferred to write-out (same operand order => bit-identical).
#define BS1 512
__global__ void __launch_bounds__(BS1) k_decode(const float* __restrict__ p3,
                                                const float* __restrict__ p4,
                                                const float* __restrict__ p5) {
    __shared__ float s_sc[NCLS * 121];   // sigmoid(cls), pad 121 -> conflict-free
    __shared__ float s_head[120 * 4];    // raw ch0-3
    __shared__ float s_obj[120];         // sigmoid(obj)

    int tile = blockIdx.x % 210;
    int b    = blockIdx.x / 210;

    const float* base;
    int W, m0, n0, abase;
    float stride;
    if (tile < 160)      { base = p3 + (size_t)b * 1632000; W = 80; m0 = tile * 120;         n0 = m0;         abase = 0; stride = 8.0f;  }
    else if (tile < 200) { base = p4 + (size_t)b * 408000;  W = 40; m0 = (tile - 160) * 120; n0 = 19200 + m0; abase = 3; stride = 16.0f; }
    else                 { base = p5 + (size_t)b * 102000;  W = 20; m0 = (tile - 200) * 120; n0 = 24000 + m0; abase = 6; stride = 32.0f; }

    const float* src = base + (size_t)m0 * 85;   // tile*10200 floats -> 16B aligned
    int t = threadIdx.x;

    // Phase B: one coalesced float4 sweep over all 10200 floats of the tile
    const float4* src4 = (const float4*)src;
    for (int i4 = t; i4 < 2550; i4 += BS1) {
        float4 v = src4[i4];
        int g0 = i4 * 4;
        float vv[4] = {v.x, v.y, v.z, v.w};
        #pragma unroll
        for (int e = 0; e < 4; e++) {
            int gg  = g0 + e;
            int anc = gg / 85;
            int ch  = gg - anc * 85;
            float ve = vv[e];
            if (ch >= 5)      s_sc[(ch - 5) * 121 + anc] = sigmoidf(ve);
            else if (ch == 4) s_obj[anc] = sigmoidf(ve);
            else              s_head[anc * 4 + ch] = ve;
        }
    }
    __syncthreads();

    // Phase A: box decode (t < 120), exact original math
    if (t < 120) {
        int m = m0 + t;
        int a = m % 3;
        int cell = m / 3;
        int w = cell % W;
        int h = cell / W;
        float sx = sigmoidf(s_head[t * 4 + 0]);
        float sy = sigmoidf(s_head[t * 4 + 1]);
        float bw = expf(s_head[t * 4 + 2]) * c_anch[(abase + a) * 2 + 0];
        float bh = expf(s_head[t * 4 + 3]) * c_anch[(abase + a) * 2 + 1];
        float cx = (sx + (float)w) * stride;
        float cy = (sy + (float)h) * stride;
        ((float4*)g_boxes)[(size_t)b * N_ANCH + n0 + t] =
            make_float4(cx - bw * 0.5f, cy - bh * 0.5f, cx + bw * 0.5f, cy + bh * 0.5f);
    }

    // Phase C: transposed coalesced write-out, obj*cls (same order as before)
    float* dst = g_scores + (size_t)b * NCLS * N_ANCH + n0;
    for (int i = t; i < 120 * NCLS; i += BS1) {
        int c = i / 120;
        int k = i - c * 120;
        dst[(size_t)c * N_ANCH + k] = s_obj[k] * s_sc[c * 121 + k];
    }
}

// ======================= Kernel 2: top-128 + NMS per (image,class) =======================
// No column staging (pass 2 re-reads via L2: 592 blocks x 100KB = 59MB < L2).
// Bitmask NMS: 128x4 suppression words built by ballots; serial scan via shfl.
#define BS2 512
#define LISTCAP 1024
__global__ void __launch_bounds__(BS2, 4) k_nms() {
    __shared__ unsigned long long list[LISTCAP];  // 8KB
    __shared__ int      hist[512];                // 2KB
    __shared__ float4   s_bx[128];                // 2KB
    __shared__ float    s_area[128];
    __shared__ float    s_cs[128];
    __shared__ unsigned s_mask[512];              // [i][word] suppression bits (j>i, iou>thr, s_i>0)
    __shared__ unsigned s_valid[4];
    __shared__ int sh_T, sh_nlist;

    int tid = threadIdx.x, lane = tid & 31, wid = tid >> 5;
    int b = blockIdx.x / NCLS;
    int c = blockIdx.x % NCLS;
    const float4* col4 = (const float4*)(g_scores + (size_t)(b * NCLS + c) * N_ANCH);

    for (int i = tid; i < 512; i += BS2) hist[i] = 0;
    if (tid == 0) sh_nlist = 0;
    __syncthreads();

    // pass 1: histogram of float-bit bins over (0.25, 1.0)
    for (int i = tid; i < N_ANCH / 4; i += BS2) {
        float4 v = col4[i];
        float vv[4] = {v.x, v.y, v.z, v.w};
        #pragma unroll
        for (int e = 0; e < 4; e++)
            if (vv[e] > 0.25f) atomicAdd(&hist[binof(vv[e])], 1);
    }
    __syncthreads();

    if (tid == 0) {
        int cum = 0, tt = 511;
        for (; tt >= 0; --tt) {
            int h = hist[tt];
            if (cum + h >= 128) break;
            cum += h;
        }
        sh_T = tt;  // -1 -> take all candidates
    }
    __syncthreads();
    int T = sh_T;

    // pass 2: re-read column (L2-resident), collect candidates in bins >= T
    for (int i = tid; i < N_ANCH / 4; i += BS2) {
        float4 v = col4[i];
        float vv[4] = {v.x, v.y, v.z, v.w};
        #pragma unroll
        for (int e = 0; e < 4; e++) {
            float ve = vv[e];
            if (ve > 0.25f && binof(ve) >= T) {
                int p = atomicAdd(&sh_nlist, 1);
                if (p < LISTCAP)
                    list[p] = ((unsigned long long)__float_as_uint(ve) << 32)
                            | (unsigned long long)(0xFFFFFFFFu - (unsigned)(4 * i + e));
            }
        }
    }
    __syncthreads();
    int L = min(sh_nlist, LISTCAP);

    int P = 128;
    while (P < L) P <<= 1;
    for (int i = L + tid; i < P; i += BS2) list[i] = 0ull;
    __syncthreads();

    // bitonic sort (width P) descending by (score_bits, ~index) = exact jax top_k order
    for (int k = 2; k <= P; k <<= 1) {
        for (int j = k >> 1; j > 0; j >>= 1) {
            for (int i = tid; i < P; i += BS2) {
                int ixj = i ^ j;
                if (ixj > i) {
                    unsigned long long a = list[i], bb = list[ixj];
                    bool dsc = ((i & k) == 0);
                    if ((a < bb) == dsc) { list[i] = bb; list[ixj] = a; }
                }
            }
            __syncthreads();
        }
    }

    // gather top-128 boxes + valid ballots
    if (tid < 128) {
        unsigned long long key = list[tid];
        float s; unsigned idx;
        if (key == 0ull) { s = -1.0f; idx = 0; }
        else {
            s = __uint_as_float((unsigned)(key >> 32));
            idx = 0xFFFFFFFFu - (unsigned)(key & 0xFFFFFFFFull);
        }
        s_cs[tid] = s;
        float4 bb = ((const float4*)g_boxes)[(size_t)b * N_ANCH + idx];
        s_bx[tid] = bb;
        s_area[tid] = (bb.z - bb.x) * (bb.w - bb.y);
        unsigned vb = __ballot_sync(0xffffffffu, s > 0.0f);
        if (lane == 0) s_valid[wid] = vb;
    }
    __syncthreads();

    // suppression masks: word = i*4 + r ; lane computes pair (i, j=r*32+lane)
    for (int it = 0; it < 32; ++it) {
        int word = wid * 32 + it;
        int i = word >> 2, r = word & 3, j = r * 32 + lane;
        bool pred = false;
        if (j > i && s_cs[i] > 0.0f) {
            float4 bi = s_bx[i], bj = s_bx[j];
            float lx = fmaxf(bi.x, bj.x), ly = fmaxf(bi.y, bj.y);
            float rx = fminf(bi.z, bj.z), ry = fminf(bi.w, bj.w);
            float w = fmaxf(rx - lx, 0.0f), h = fmaxf(ry - ly, 0.0f);
            float inter = w * h;
            float iou = inter / (s_area[i] + s_area[j] - inter + 1e-9f);
            pred = iou > 0.45f;
        }
        unsigned mw = __ballot_sync(0xffffffffu, pred);
        if (lane == 0) s_mask[word] = mw;
    }
    __syncthreads();

    // serial NMS scan over 128 rows, masks lane-distributed, keep-words replicated
    if (tid < 32) {
        unsigned m0r[4], m1r[4], m2r[4], m3r[4];
        #pragma unroll
        for (int r = 0; r < 4; r++) {
            m0r[r] = s_mask[(lane      ) * 4 + r];
            m1r[r] = s_mask[(lane +  32) * 4 + r];
            m2r[r] = s_mask[(lane +  64) * 4 + r];
            m3r[r] = s_mask[(lane +  96) * 4 + r];
        }
        unsigned k0 = ~0u, k1 = ~0u, k2 = ~0u, k3 = ~0u;
        #pragma unroll
        for (int s = 0; s < 32; s++) {           // rows 0..31 (keep bits uniform across lanes)
            if ((k0 >> s) & 1u) {
                k0 &= ~__shfl_sync(0xffffffffu, m0r[0], s);
                k1 &= ~__shfl_sync(0xffffffffu, m0r[1], s);
                k2 &= ~__shfl_sync(0xffffffffu, m0r[2], s);
                k3 &= ~__shfl_sync(0xffffffffu, m0r[3], s);
            }
        }
        #pragma unroll
        for (int s = 0; s < 32; s++) {           // rows 32..63
            if ((k1 >> s) & 1u) {
                k0 &= ~__shfl_sync(0xffffffffu, m1r[0], s);
                k1 &= ~__shfl_sync(0xffffffffu, m1r[1], s);
                k2 &= ~__shfl_sync(0xffffffffu, m1r[2], s);
                k3 &= ~__shfl_sync(0xffffffffu, m1r[3], s);
            }
        }
        #pragma unroll
        for (int s = 0; s < 32; s++) {           // rows 64..95
            if ((k2 >> s) & 1u) {
                k0 &= ~__shfl_sync(0xffffffffu, m2r[0], s);
                k1 &= ~__shfl_sync(0xffffffffu, m2r[1], s);
                k2 &= ~__shfl_sync(0xffffffffu, m2r[2], s);
                k3 &= ~__shfl_sync(0xffffffffu, m2r[3], s);
            }
        }
        #pragma unroll
        for (int s = 0; s < 32; s++) {           // rows 96..127
            if ((k3 >> s) & 1u) {
                k0 &= ~__shfl_sync(0xffffffffu, m3r[0], s);
                k1 &= ~__shfl_sync(0xffffffffu, m3r[1], s);
                k2 &= ~__shfl_sync(0xffffffffu, m3r[2], s);
                k3 &= ~__shfl_sync(0xffffffffu, m3r[3], s);
            }
        }

        unsigned sv[4] = { k0 & s_valid[0], k1 & s_valid[1], k2 & s_valid[2], k3 & s_valid[3] };
        float* outS = g_cls_s + (size_t)(b * NCLS + c) * 100;
        float4* outB = ((float4*)g_cls_b) + (size_t)(b * NCLS + c) * 100;
        int base = 0;
        #pragma unroll
        for (int q = 0; q < 4; ++q) {
            unsigned m = sv[q];
            if ((m >> lane) & 1u) {
                int pos = base + __popc(m & ((1u << lane) - 1u));
                if (pos < 100) { outS[pos] = s_cs[lane + 32 * q]; outB[pos] = s_bx[lane + 32 * q]; }
            }
            base += __popc(m);
        }
        int ns = min(base, 100);
        for (int p = ns + lane; p < 100; p += 32) {
            outS[p] = -1.0f;
            outB[p] = make_float4(0, 0, 0, 0);
        }
    }
}

// ======================= Kernel 3: per-image final top-100 (hist select) =======================
#define BS3 512
__global__ void __launch_bounds__(BS3) k_final(float* __restrict__ out) {
    __shared__ unsigned long long list[LISTCAP];
    __shared__ int hist[512];
    __shared__ int sh_T, sh_nlist, s_cnt;

    int tid = threadIdx.x;
    int b = blockIdx.x;
    const float* cs = g_cls_s + (size_t)b * 8000;

    for (int i = tid; i < 512; i += BS3) hist[i] = 0;
    if (tid == 0) { sh_nlist = 0; s_cnt = 0; }
    __syncthreads();

    for (int i = tid; i < 8000; i += BS3) {
        float v = cs[i];                      // valid scores are all > 0.25
        if (v > 0.25f) atomicAdd(&hist[binof(v)], 1);
    }
    __syncthreads();

    if (tid == 0) {
        int cum = 0, tt = 511;
        for (; tt >= 0; --tt) {
            int h = hist[tt];
            if (cum + h >= 100) break;
            cum += h;
        }
        sh_T = tt;
    }
    __syncthreads();
    int T = sh_T;

    for (int i = tid; i < 8000; i += BS3) {
        float v = cs[i];
        if (v > 0.25f && binof(v) >= T) {
            int p = atomicAdd(&sh_nlist, 1);
            if (p < LISTCAP)
                list[p] = ((unsigned long long)__float_as_uint(v) << 32)
                        | (unsigned long long)(0xFFFFFFFFu - (unsigned)i);
        }
    }
    __syncthreads();
    int L = min(sh_nlist, LISTCAP);
    int P = 128;
    while (P < L) P <<= 1;
    for (int i = L + tid; i < P; i += BS3) list[i] = 0ull;
    __syncthreads();

    for (int k = 2; k <= P; k <<= 1) {
        for (int j = k >> 1; j > 0; j >>= 1) {
            for (int i = tid; i < P; i += BS3) {
                int ixj = i ^ j;
                if (ixj > i) {
                    unsigned long long a = list[i], bb = list[ixj];
                    bool dsc = ((i & k) == 0);
                    if ((a < bb) == dsc) { list[i] = bb; list[ixj] = a; }
                }
            }
            __syncthreads();
        }
    }

    if (tid < 100) {
        unsigned long long key = list[tid];
        float4 box = make_float4(0, 0, 0, 0);
        float score = 0.0f, clsf = 0.0f;
        if (key != 0ull) {
            float v = __uint_as_float((unsigned)(key >> 32));
            unsigned flat = 0xFFFFFFFFu - (unsigned)(key & 0xFFFFFFFFull);
            box = ((const float4*)g_cls_b)[(size_t)b * 8000 + flat];
            score = v;
            clsf = (float)(flat / 100u);
            atomicAdd(&s_cnt, 1);
        }
        ((float4*)out)[b * 100 + tid] = box;                 // boxes  [0, 6400)
        out[6400 + b * 100 + tid] = score;                   // scores [6400, 8000)
        out[8000 + b * 100 + tid] = clsf;                    // cls    [8000, 9600)
    }
    __syncthreads();
    if (tid == 0) out[9600 + b] = (float)s_cnt;              // n_valid [9600, 9616)
}

// ======================= launch =======================
extern "C" void kernel_launch(void* const* d_in, const int* in_sizes, int n_in,
                              void* d_out, int out_size) {
    const float* p3 = (const float*)d_in[0];
    const float* p4 = (const float*)d_in[1];
    const float* p5 = (const float*)d_in[2];
    float* out = (float*)d_out;

    k_decode<<<NBATCH * 210, BS1>>>(p3, p4, p5);
    k_nms<<<NBATCH * NCLS, BS2>>>();
    k_final<<<NBATCH, BS3>>>(out);
}